// round 1
// baseline (speedup 1.0000x reference)
#include <cuda_runtime.h>
#include <cstdint>
#include <cstddef>

// ---------------------------------------------------------------------------
// Problem constants
// ---------------------------------------------------------------------------
#define Sq      1024
#define Hd      4096
#define NHEAD   32
#define HDIM    128
#define RLORA   16
#define NELEM   (Sq * Hd)            // 4194304
#define WELEM   (Hd * Hd)            // 16777216
#define AELEM   ((size_t)NHEAD * Sq * Sq)   // 33554432

// ---------------------------------------------------------------------------
// Device scratch (static: no allocation allowed)
// ---------------------------------------------------------------------------
__device__ float g_Wd[WELEM];                 // dequantized weight (reused x4)
__device__ float g_q[NELEM];
__device__ float g_k[NELEM];
__device__ float g_v[NELEM];
__device__ float g_o[NELEM];                  // attention output (pre o-proj)
__device__ float g_attn[AELEM];               // scores -> probs
__device__ float g_xa[Sq * RLORA];            // x @ lora_a

// selection state
__device__ unsigned long long g_ksel;
__device__ unsigned           g_prefix;
__device__ unsigned           g_hist[2048];

__constant__ float c_nf4[16] = {
    -1.0f, -0.6961928009986877f, -0.5250730514526367f, -0.39491748809814453f,
    -0.28444138169288635f, -0.18477343022823334f, -0.09105003625154495f, 0.0f,
    0.07958029955625534f, 0.16093020141124725f, 0.24611230194568634f,
    0.33791524171829224f, 0.4407098591327667f, 0.5626170039176941f,
    0.7229568362236023f, 1.0f };

// ---------------------------------------------------------------------------
// NF4 dequant: W[j,i] = nf4[codes[j*H+i]] * absmax[(j*H+i)>>6]
// ---------------------------------------------------------------------------
__global__ void dequant_kernel(const int* __restrict__ codes,
                               const float* __restrict__ absmax,
                               float* __restrict__ W)
{
    size_t t = (size_t)blockIdx.x * blockDim.x + threadIdx.x;
    size_t base = t * 4;
    if (base >= (size_t)WELEM) return;
    int4 c = *(const int4*)(codes + base);
    float am = absmax[base >> 6];             // 4 consecutive elems share block
    float4 o;
    o.x = c_nf4[c.x & 15] * am;
    o.y = c_nf4[c.y & 15] * am;
    o.z = c_nf4[c.z & 15] * am;
    o.w = c_nf4[c.w & 15] * am;
    *(float4*)(W + base) = o;
}

// ---------------------------------------------------------------------------
// xa = X @ lora_a    X:[1024,4096], la:[4096,16] -> xa:[1024,16]
// one block per row; thread = (chunk 0..15, r 0..15)
// ---------------------------------------------------------------------------
__global__ void lora_xa_kernel(const float* __restrict__ X,
                               const float* __restrict__ la,
                               float* __restrict__ xa)
{
    int s = blockIdx.x;
    int r = threadIdx.x & 15;
    int chunk = threadIdx.x >> 4;
    float sum = 0.f;
    int i0 = chunk * 256;
    const float* xr = X + (size_t)s * Hd;
    for (int i = i0; i < i0 + 256; i++)
        sum += xr[i] * la[(size_t)i * RLORA + r];
    __shared__ float red[256];
    red[threadIdx.x] = sum;
    __syncthreads();
    for (int off = 128; off >= 16; off >>= 1) {
        if (threadIdx.x < off) red[threadIdx.x] += red[threadIdx.x + off];
        __syncthreads();
    }
    if (threadIdx.x < 16) xa[(size_t)s * RLORA + threadIdx.x] = red[threadIdx.x];
}

// ---------------------------------------------------------------------------
// Projection GEMM:  C[1024,4096] = X[1024,4096] * W^T  + bias + xa*lb
// W stored [N=4096, K=4096] row-major (K contiguous) -> NT GEMM.
// Tile 128x128x16, 256 threads, 8x8 per thread.
// ---------------------------------------------------------------------------
#define BM 128
#define BN 128
#define BKT 16

__global__ __launch_bounds__(256)
void gemm_proj_kernel(const float* __restrict__ A,
                      const float* __restrict__ W,
                      const float* __restrict__ bias,
                      const float* __restrict__ xa,
                      const float* __restrict__ lb,
                      float* __restrict__ C)
{
    const int Kd = Hd, Nd = Hd;
    int bm = blockIdx.y * BM;
    int bn = blockIdx.x * BN;
    int tid = threadIdx.x;
    int tx = tid & 15, ty = tid >> 4;
    __shared__ float As[BKT][BM];
    __shared__ float Bs[BKT][BN];
    float acc[8][8] = {};

    for (int k0 = 0; k0 < Kd; k0 += BKT) {
#pragma unroll
        for (int l = 0; l < 2; l++) {
            int f = tid + l * 256;            // float4 slot (512 total)
            int r = f >> 2, c4 = f & 3;
            float4 v = *(const float4*)(A + (size_t)(bm + r) * Kd + k0 + c4 * 4);
            As[c4 * 4 + 0][r] = v.x; As[c4 * 4 + 1][r] = v.y;
            As[c4 * 4 + 2][r] = v.z; As[c4 * 4 + 3][r] = v.w;
        }
#pragma unroll
        for (int l = 0; l < 2; l++) {
            int f = tid + l * 256;
            int r = f >> 2, c4 = f & 3;
            float4 v = *(const float4*)(W + (size_t)(bn + r) * Kd + k0 + c4 * 4);
            Bs[c4 * 4 + 0][r] = v.x; Bs[c4 * 4 + 1][r] = v.y;
            Bs[c4 * 4 + 2][r] = v.z; Bs[c4 * 4 + 3][r] = v.w;
        }
        __syncthreads();
#pragma unroll
        for (int kk = 0; kk < BKT; kk++) {
            float ar[8], br[8];
#pragma unroll
            for (int i = 0; i < 8; i++) ar[i] = As[kk][ty * 8 + i];
#pragma unroll
            for (int j = 0; j < 8; j++) br[j] = Bs[kk][tx * 8 + j];
#pragma unroll
            for (int i = 0; i < 8; i++)
#pragma unroll
                for (int j = 0; j < 8; j++)
                    acc[i][j] += ar[i] * br[j];
        }
        __syncthreads();
    }
#pragma unroll
    for (int i = 0; i < 8; i++) {
        int row = bm + ty * 8 + i;
        float xav[RLORA];
#pragma unroll
        for (int r = 0; r < RLORA; r++) xav[r] = xa[(size_t)row * RLORA + r];
#pragma unroll
        for (int j = 0; j < 8; j++) {
            int col = bn + tx * 8 + j;
            float v = acc[i][j] + bias[col];
#pragma unroll
            for (int r = 0; r < RLORA; r++) v += xav[r] * lb[(size_t)r * Nd + col];
            C[(size_t)row * Nd + col] = v;
        }
    }
}

// ---------------------------------------------------------------------------
// Scores: S[h,q,k] = (Qh . Kh)/sqrt(128) + mask[q,k]
// Qh rows stride 4096, K=128. NT GEMM per head.
// ---------------------------------------------------------------------------
__global__ __launch_bounds__(256)
void gemm_scores_kernel(const float* __restrict__ Q,
                        const float* __restrict__ Kb,
                        const float* __restrict__ mask,
                        float* __restrict__ S)
{
    const int Kd = HDIM;
    int h = blockIdx.z;
    const float* A = Q + (size_t)h * HDIM;
    const float* B = Kb + (size_t)h * HDIM;
    float* Sh = S + (size_t)h * Sq * Sq;
    int bm = blockIdx.y * BM;
    int bn = blockIdx.x * BN;
    int tid = threadIdx.x;
    int tx = tid & 15, ty = tid >> 4;
    __shared__ float As[BKT][BM];
    __shared__ float Bs[BKT][BN];
    float acc[8][8] = {};
    for (int k0 = 0; k0 < Kd; k0 += BKT) {
#pragma unroll
        for (int l = 0; l < 2; l++) {
            int f = tid + l * 256;
            int r = f >> 2, c4 = f & 3;
            float4 v = *(const float4*)(A + (size_t)(bm + r) * Hd + k0 + c4 * 4);
            As[c4 * 4 + 0][r] = v.x; As[c4 * 4 + 1][r] = v.y;
            As[c4 * 4 + 2][r] = v.z; As[c4 * 4 + 3][r] = v.w;
        }
#pragma unroll
        for (int l = 0; l < 2; l++) {
            int f = tid + l * 256;
            int r = f >> 2, c4 = f & 3;
            float4 v = *(const float4*)(B + (size_t)(bn + r) * Hd + k0 + c4 * 4);
            Bs[c4 * 4 + 0][r] = v.x; Bs[c4 * 4 + 1][r] = v.y;
            Bs[c4 * 4 + 2][r] = v.z; Bs[c4 * 4 + 3][r] = v.w;
        }
        __syncthreads();
#pragma unroll
        for (int kk = 0; kk < BKT; kk++) {
            float ar[8], br[8];
#pragma unroll
            for (int i = 0; i < 8; i++) ar[i] = As[kk][ty * 8 + i];
#pragma unroll
            for (int j = 0; j < 8; j++) br[j] = Bs[kk][tx * 8 + j];
#pragma unroll
            for (int i = 0; i < 8; i++)
#pragma unroll
                for (int j = 0; j < 8; j++)
                    acc[i][j] += ar[i] * br[j];
        }
        __syncthreads();
    }
    const float scale = 0.08838834764831845f;   // 1/sqrt(128)
#pragma unroll
    for (int i = 0; i < 8; i++) {
        int row = bm + ty * 8 + i;
#pragma unroll
        for (int j = 0; j < 8; j++) {
            int col = bn + tx * 8 + j;
            Sh[(size_t)row * Sq + col] =
                acc[i][j] * scale + mask[(size_t)row * Sq + col];
        }
    }
}

// ---------------------------------------------------------------------------
// Row softmax over 1024 cols, in place. One 256-thread block per row.
// ---------------------------------------------------------------------------
__global__ void softmax_kernel(float* __restrict__ S)
{
    size_t row = blockIdx.x;
    float* p = S + row * Sq;
    int tid = threadIdx.x;
    __shared__ float red[256];
    float lmax = -3.4e38f;
    for (int i = tid; i < Sq; i += 256) lmax = fmaxf(lmax, p[i]);
    red[tid] = lmax; __syncthreads();
    for (int off = 128; off > 0; off >>= 1) {
        if (tid < off) red[tid] = fmaxf(red[tid], red[tid + off]);
        __syncthreads();
    }
    float m = red[0]; __syncthreads();
    float lsum = 0.f;
    for (int i = tid; i < Sq; i += 256) {
        float e = expf(p[i] - m);
        p[i] = e;
        lsum += e;
    }
    red[tid] = lsum; __syncthreads();
    for (int off = 128; off > 0; off >>= 1) {
        if (tid < off) red[tid] += red[tid + off];
        __syncthreads();
    }
    float inv = 1.0f / red[0];
    for (int i = tid; i < Sq; i += 256) p[i] *= inv;
}

// ---------------------------------------------------------------------------
// O = P @ Vh per head.  P:[1024,1024] (K contig), Vh:[k,d] row stride 4096
// (N contiguous -> NN GEMM). BN=128 covers full head dim.
// ---------------------------------------------------------------------------
__global__ __launch_bounds__(256)
void gemm_pv_kernel(const float* __restrict__ P,
                    const float* __restrict__ V,
                    float* __restrict__ O)
{
    const int Kd = Sq;
    int h = blockIdx.z;
    const float* A = P + (size_t)h * Sq * Sq;
    int bm = blockIdx.y * BM;
    int tid = threadIdx.x;
    int tx = tid & 15, ty = tid >> 4;
    __shared__ float As[BKT][BM];
    __shared__ float Bs[BKT][BN];
    float acc[8][8] = {};
    for (int k0 = 0; k0 < Kd; k0 += BKT) {
#pragma unroll
        for (int l = 0; l < 2; l++) {
            int f = tid + l * 256;
            int r = f >> 2, c4 = f & 3;
            float4 v = *(const float4*)(A + (size_t)(bm + r) * Sq + k0 + c4 * 4);
            As[c4 * 4 + 0][r] = v.x; As[c4 * 4 + 1][r] = v.y;
            As[c4 * 4 + 2][r] = v.z; As[c4 * 4 + 3][r] = v.w;
        }
        // B tile: rows k0..k0+15, 128 contiguous d values
#pragma unroll
        for (int l = 0; l < 2; l++) {
            int f = tid + l * 256;
            int r = f >> 5, n4 = f & 31;     // r 0..15, n4 0..31
            float4 v = *(const float4*)(V + (size_t)(k0 + r) * Hd + h * HDIM + n4 * 4);
            *(float4*)&Bs[r][n4 * 4] = v;
        }
        __syncthreads();
#pragma unroll
        for (int kk = 0; kk < BKT; kk++) {
            float ar[8], br[8];
#pragma unroll
            for (int i = 0; i < 8; i++) ar[i] = As[kk][ty * 8 + i];
#pragma unroll
            for (int j = 0; j < 8; j++) br[j] = Bs[kk][tx * 8 + j];
#pragma unroll
            for (int i = 0; i < 8; i++)
#pragma unroll
                for (int j = 0; j < 8; j++)
                    acc[i][j] += ar[i] * br[j];
        }
        __syncthreads();
    }
#pragma unroll
    for (int i = 0; i < 8; i++) {
        int row = bm + ty * 8 + i;
#pragma unroll
        for (int j = 0; j < 8; j++) {
            int col = tx * 8 + j;             // 0..127 = head dim
            O[(size_t)row * Hd + h * HDIM + col] = acc[i][j];
        }
    }
}

// ---------------------------------------------------------------------------
// Exact rank-k selection via 3-pass radix select on float bits (nonneg data).
// ---------------------------------------------------------------------------
__global__ void sel_init(unsigned long long k)
{
    int t = blockIdx.x * blockDim.x + threadIdx.x;
    if (t < 2048) g_hist[t] = 0;
    if (t == 0) { g_ksel = k; g_prefix = 0u; }
}

__global__ void sel_hist(const float* __restrict__ data, size_t n,
                         unsigned mask, int shift, int bits)
{
    __shared__ unsigned sh[2048];
    for (int i = threadIdx.x; i < 2048; i += blockDim.x) sh[i] = 0;
    __syncthreads();
    unsigned pref = g_prefix;
    unsigned nb = (1u << bits) - 1u;
    size_t stride = (size_t)gridDim.x * blockDim.x;
    unsigned zc = 0;
    for (size_t i = (size_t)blockIdx.x * blockDim.x + threadIdx.x; i < n; i += stride) {
        unsigned u = __float_as_uint(data[i]) & 0x7FFFFFFFu;
        if ((u & mask) == pref) {
            if (u == 0u) zc++;                        // heavy zero mass (softmax)
            else atomicAdd(&sh[(u >> shift) & nb], 1u);
        }
    }
    if (zc) atomicAdd(&sh[0], zc);                    // u==0 => pref==0, bin 0
    __syncthreads();
    for (int i = threadIdx.x; i < (1 << bits); i += blockDim.x)
        if (sh[i]) atomicAdd(&g_hist[i], sh[i]);
}

__global__ void sel_pick(int shift, float* out)
{
    __shared__ unsigned h[2048];
    for (int i = threadIdx.x; i < 2048; i += blockDim.x) {
        h[i] = g_hist[i];
        g_hist[i] = 0;                                // ready for next pass
    }
    __syncthreads();
    if (threadIdx.x == 0) {
        unsigned long long k = g_ksel;
        unsigned long long cum = 0;
        int sel = 0;
        for (int b = 0; b < 2048; b++) {
            if (cum + h[b] >= k) { sel = b; break; }
            cum += h[b];
        }
        g_ksel = k - cum;
        unsigned pref = g_prefix | ((unsigned)sel << shift);
        g_prefix = pref;
        if (out) *out = __uint_as_float(pref);
    }
}

// ---------------------------------------------------------------------------
// Host orchestration
// ---------------------------------------------------------------------------
static void run_select(const float* data, size_t n, unsigned long long k, float* out)
{
    sel_init<<<2, 1024>>>(k);
    sel_hist<<<1024, 256>>>(data, n, 0u,           21, 11);
    sel_pick<<<1, 1024>>>(21, nullptr);
    sel_hist<<<1024, 256>>>(data, n, 0xFFE00000u,  10, 11);
    sel_pick<<<1, 1024>>>(10, nullptr);
    sel_hist<<<1024, 256>>>(data, n, 0xFFFFFC00u,   0, 10);
    sel_pick<<<1, 1024>>>(0, out);
}

extern "C" void kernel_launch(void* const* d_in, const int* in_sizes, int n_in,
                              void* d_out, int out_size)
{
    const float* x    = (const float*)d_in[0];
    // q,k,v,o blocks of 5: codes, absmax, bias, lora_a, lora_b
    const int*   codes[4];
    const float *amax[4], *bias[4], *la[4], *lb[4];
    for (int p = 0; p < 4; p++) {
        codes[p] = (const int*)  d_in[1 + p * 5 + 0];
        amax[p]  = (const float*)d_in[1 + p * 5 + 1];
        bias[p]  = (const float*)d_in[1 + p * 5 + 2];
        la[p]    = (const float*)d_in[1 + p * 5 + 3];
        lb[p]    = (const float*)d_in[1 + p * 5 + 4];
    }
    const float* mask = (const float*)d_in[21];
    float* out = (float*)d_out;

    float *pWd, *pQ, *pK, *pV, *pO, *pAttn, *pXa;
    cudaGetSymbolAddress((void**)&pWd,   g_Wd);
    cudaGetSymbolAddress((void**)&pQ,    g_q);
    cudaGetSymbolAddress((void**)&pK,    g_k);
    cudaGetSymbolAddress((void**)&pV,    g_v);
    cudaGetSymbolAddress((void**)&pO,    g_o);
    cudaGetSymbolAddress((void**)&pAttn, g_attn);
    cudaGetSymbolAddress((void**)&pXa,   g_xa);

    dim3 gproj(Hd / BN, Sq / BM);          // (32, 8)
    float* qkv[3] = { pQ, pK, pV };

    // --- Q, K, V projections ---
    for (int p = 0; p < 3; p++) {
        dequant_kernel<<<WELEM / 4 / 256, 256>>>(codes[p], amax[p], pWd);
        lora_xa_kernel<<<Sq, 256>>>(x, la[p], pXa);
        gemm_proj_kernel<<<gproj, 256>>>(x, pWd, bias[p], pXa, lb[p], qkv[p]);
    }

    // --- Attention ---
    gemm_scores_kernel<<<dim3(Sq / BN, Sq / BM, NHEAD), 256>>>(pQ, pK, mask, pAttn);
    softmax_kernel<<<NHEAD * Sq, 256>>>(pAttn);
    gemm_pv_kernel<<<dim3(1, Sq / BM, NHEAD), 256>>>(pAttn, pV, pO);

    // --- Output projection (writes d_out[0 .. NELEM)) ---
    dequant_kernel<<<WELEM / 4 / 256, 256>>>(codes[3], amax[3], pWd);
    lora_xa_kernel<<<Sq, 256>>>(pO, la[3], pXa);
    gemm_proj_kernel<<<gproj, 256>>>(pO, pWd, bias[3], pXa, lb[3], out);

    // --- kth values: [x, qh, kh, vh, a, o] ---
    const unsigned long long kN = NELEM / 2;          // 2097152
    const unsigned long long kA = AELEM / 2;          // 16777216
    run_select(x,     NELEM, kN, out + NELEM + 0);
    run_select(pQ,    NELEM, kN, out + NELEM + 1);
    run_select(pK,    NELEM, kN, out + NELEM + 2);
    run_select(pV,    NELEM, kN, out + NELEM + 3);
    run_select(pAttn, AELEM, kA, out + NELEM + 4);
    run_select(pO,    NELEM, kN, out + NELEM + 5);
}

// round 3
// speedup vs baseline: 3.8645x; 3.8645x over previous
#include <cuda_runtime.h>
#include <cstdint>
#include <cstddef>

// ---------------------------------------------------------------------------
// Problem constants
// ---------------------------------------------------------------------------
#define Sq      1024
#define Hd      4096
#define NHEAD   32
#define HDIM    128
#define RLORA   16
#define NELEM   (Sq * Hd)                   // 4194304
#define WELEM   (Hd * Hd)                   // 16777216
#define AELEM   ((size_t)NHEAD * Sq * Sq)   // 33554432
#define KAUG    4128                        // 4096 + 32 (lora tail, zero padded)

// Arch-specific (sm_103a) feature gate: tcgen05 only exists in the
// arch-specific compilation pass. The generic compute_103 pass gets an
// FFMA fallback body so every embedded cubin/PTX is valid AND correct.
#if defined(__CUDA_ARCH_FEAT_SM103_ALL) || defined(__CUDA_ARCH_FEAT_SM100_ALL) || \
    defined(__CUDA_ARCH_FEAT_SM101_ALL)
#define TC_OK 1
#else
#define TC_OK 0
#endif

// ---------------------------------------------------------------------------
// Device scratch (static: no allocation allowed)
// ---------------------------------------------------------------------------
__device__ float g_Aaug[Sq * KAUG];           // [1024,4128] rounded A (x, later o)
__device__ float g_Baug[Hd * KAUG];           // [4096,4128] dequant W + lb^T tail
__device__ float g_q[NELEM];
__device__ float g_k[NELEM];
__device__ float g_v[NELEM];
__device__ float g_vt[NELEM];                 // V transposed: [4096 d][1024 k]
__device__ float g_attn[AELEM];               // scores -> probs (tf32-rounded)
__device__ float g_xa[Sq * RLORA];            // x @ lora_a

// selection state
__device__ unsigned long long g_ksel;
__device__ unsigned           g_prefix;
__device__ unsigned           g_hist[2048];

__constant__ float c_nf4[16] = {
    -1.0f, -0.6961928009986877f, -0.5250730514526367f, -0.39491748809814453f,
    -0.28444138169288635f, -0.18477343022823334f, -0.09105003625154495f, 0.0f,
    0.07958029955625534f, 0.16093020141124725f, 0.24611230194568634f,
    0.33791524171829224f, 0.4407098591327667f, 0.5626170039176941f,
    0.7229568362236023f, 1.0f };

// ---------------------------------------------------------------------------
// PTX helpers
// ---------------------------------------------------------------------------
__device__ __forceinline__ uint32_t smem_u32(const void* p) {
    uint32_t a;
    asm("{ .reg .u64 t; cvta.to.shared.u64 t, %1; cvt.u32.u64 %0, t; }"
        : "=r"(a) : "l"(p));
    return a;
}
__device__ __forceinline__ bool elect_one() {
    uint32_t pred;
    asm volatile("{\n\t.reg .pred p;\n\telect.sync _|p, 0xFFFFFFFF;\n\t"
                 "selp.b32 %0, 1, 0, p;\n\t}" : "=r"(pred));
    return pred != 0;
}
__device__ __forceinline__ float tf32r(float v) {
    unsigned u;
    asm("cvt.rna.tf32.f32 %0, %1;" : "=r"(u) : "f"(v));
    return __uint_as_float(u);
}
__device__ __forceinline__ unsigned swz(unsigned off) {   // SW128 swizzle
    return off ^ ((off >> 3) & 0x70);
}
__device__ __forceinline__ void cpa16(unsigned dst, const void* src) {
    asm volatile("cp.async.cg.shared.global [%0], [%1], 16;"
                 :: "r"(dst), "l"(src));
}

static constexpr uint64_t SMEM_DESC_BASE_SW128 =
    (uint64_t(2)  << 61) | (uint64_t(1) << 46) |
    (uint64_t(64) << 32) | (uint64_t(1) << 16);
#define MAKE_SMEM_DESC(base_addr) \
    (SMEM_DESC_BASE_SW128 | ((uint64_t)((base_addr) >> 4) & 0x3FFF))

#define MBARRIER_INIT(mbar, count) \
    asm volatile("mbarrier.init.shared.b64 [%0], %1;" \
        :: "r"((uint32_t)(mbar)), "r"((uint32_t)(count)) : "memory")
#define MBARRIER_WAIT_PARITY(mbar_smem_addr, phase_parity) do { \
    uint32_t _mbar = (uint32_t)(mbar_smem_addr); \
    uint32_t _parity = (uint32_t)(phase_parity); \
    uint32_t _done; \
    asm volatile("{\n\t.reg .pred p;\n\t" \
        "mbarrier.try_wait.parity.acquire.cta.shared::cta.b64 p, [%1], %2;\n\t" \
        "selp.b32 %0, 1, 0, p;\n\t}" \
        : "=r"(_done) : "r"(_mbar), "r"(_parity) : "memory"); \
    if (!_done) { \
        asm volatile("{\n\t.reg .pred P1;\n\t" \
            "WAIT_LOOP_%=:\n\t" \
            "mbarrier.try_wait.parity.acquire.cta.shared::cta.b64 P1, [%0], %1, 0x989680;\n\t" \
            "@P1 bra.uni WAIT_DONE_%=;\n\t" \
            "bra.uni WAIT_LOOP_%=;\n\t" \
            "WAIT_DONE_%=:\n\t}" \
            :: "r"(_mbar), "r"(_parity) : "memory"); \
    } \
} while (0)

#if TC_OK
#define TCGEN05_ALLOC(smem_result_addr, nCols) \
    asm volatile("tcgen05.alloc.cta_group::1.sync.aligned.shared::cta.b32 [%0], %1;" \
        :: "r"((uint32_t)(smem_result_addr)), "r"((uint32_t)(nCols)) : "memory")
#define TCGEN05_DEALLOC(tmem_addr, nCols) \
    asm volatile("tcgen05.dealloc.cta_group::1.sync.aligned.b32 %0, %1;" \
        :: "r"(tmem_addr), "r"((uint32_t)(nCols)))
#define TCGEN05_RELINQUISH() \
    asm volatile("tcgen05.relinquish_alloc_permit.cta_group::1.sync.aligned;")
#define TCGEN05_COMMIT(mbar) \
    asm volatile("tcgen05.commit.cta_group::1.mbarrier::arrive::one.shared::cluster.b64 [%0];" \
        :: "r"((uint32_t)(mbar)) : "memory")
#define TCGEN05_FENCE_AFTER() \
    asm volatile("tcgen05.fence::after_thread_sync;" ::: "memory")
#define TCGEN05_WAIT_LD() \
    asm volatile("tcgen05.wait::ld.sync.aligned;" ::: "memory")
#define FENCE_PROXY_ASYNC() \
    asm volatile("fence.proxy.async.shared::cta;" ::: "memory")

#define TCGEN05_LD_32X32B_X32(r, tmem_addr) \
    asm volatile( \
        "tcgen05.ld.sync.aligned.32x32b.x32.b32 " \
        "{%0, %1, %2, %3, %4, %5, %6, %7, " \
        " %8, %9, %10, %11, %12, %13, %14, %15, " \
        " %16, %17, %18, %19, %20, %21, %22, %23, " \
        " %24, %25, %26, %27, %28, %29, %30, %31}, [%32];" \
        : "=r"((r)[0]),  "=r"((r)[1]),  "=r"((r)[2]),  "=r"((r)[3]), \
          "=r"((r)[4]),  "=r"((r)[5]),  "=r"((r)[6]),  "=r"((r)[7]), \
          "=r"((r)[8]),  "=r"((r)[9]),  "=r"((r)[10]), "=r"((r)[11]), \
          "=r"((r)[12]), "=r"((r)[13]), "=r"((r)[14]), "=r"((r)[15]), \
          "=r"((r)[16]), "=r"((r)[17]), "=r"((r)[18]), "=r"((r)[19]), \
          "=r"((r)[20]), "=r"((r)[21]), "=r"((r)[22]), "=r"((r)[23]), \
          "=r"((r)[24]), "=r"((r)[25]), "=r"((r)[26]), "=r"((r)[27]), \
          "=r"((r)[28]), "=r"((r)[29]), "=r"((r)[30]), "=r"((r)[31]) \
        : "r"(tmem_addr))

__device__ __forceinline__ void mma_tf32(uint32_t d, uint64_t ad, uint64_t bd,
                                         uint32_t idesc, uint32_t en)
{
    asm volatile(
        "{\n\t"
        ".reg .pred p;\n\t"
        "setp.ne.u32 p, %5, 0;\n\t"
        "tcgen05.mma.cta_group::1.kind::tf32 [%0], %1, %2, %3, {%4, %4, %4, %4}, p;\n\t"
        "}"
        :: "r"(d), "l"(ad), "l"(bd), "r"(idesc), "r"(0u), "r"(en)
        : "memory");
}
#endif // TC_OK

// ---------------------------------------------------------------------------
// NF4 dequant -> B_aug (stride KAUG), tf32-rounded. 16 elems/thread.
// ---------------------------------------------------------------------------
__global__ void dequant_kernel(const int* __restrict__ codes,
                               const float* __restrict__ absmax,
                               float* __restrict__ W)
{
    size_t t = (size_t)blockIdx.x * blockDim.x + threadIdx.x;
    size_t base = t * 16;
    if (base >= (size_t)WELEM) return;
    float am = absmax[base >> 6];            // 16 consecutive share one block
    size_t row = base >> 12, col = base & 4095;
    float* dst = W + row * KAUG + col;
#pragma unroll
    for (int q = 0; q < 4; q++) {
        int4 c = *(const int4*)(codes + base + q * 4);
        float4 o;
        o.x = tf32r(c_nf4[c.x & 15] * am);
        o.y = tf32r(c_nf4[c.y & 15] * am);
        o.z = tf32r(c_nf4[c.z & 15] * am);
        o.w = tf32r(c_nf4[c.w & 15] * am);
        *(float4*)(dst + q * 4) = o;
    }
}

// ---------------------------------------------------------------------------
// Round x (fp32 -> tf32) into A_aug [1024, KAUG]
// ---------------------------------------------------------------------------
__global__ void roundx_kernel(const float* __restrict__ x, float* __restrict__ Aa)
{
    size_t t = (size_t)blockIdx.x * blockDim.x + threadIdx.x;
    size_t base = t * 4;
    if (base >= (size_t)NELEM) return;
    float4 v = *(const float4*)(x + base);
    float4 o = make_float4(tf32r(v.x), tf32r(v.y), tf32r(v.z), tf32r(v.w));
    size_t row = base >> 12, col = base & 4095;
    *(float4*)(Aa + row * KAUG + col) = o;
}

// A_aug lora tail: cols 4096..4127 <- xa (tf32) | zeros
__global__ void tailA_kernel(const float* __restrict__ xa, float* __restrict__ Aa)
{
    int row = blockIdx.x, r = threadIdx.x;
    float v = (r < RLORA) ? tf32r(xa[row * RLORA + r]) : 0.f;
    Aa[(size_t)row * KAUG + 4096 + r] = v;
}
// B_aug lora tail: cols 4096..4127 <- lb^T (tf32) | zeros
__global__ void tailB_kernel(const float* __restrict__ lb, float* __restrict__ Ba)
{
    int n = blockIdx.x, r = threadIdx.x;
    float v = (r < RLORA) ? tf32r(lb[(size_t)r * Hd + n]) : 0.f;
    Ba[(size_t)n * KAUG + 4096 + r] = v;
}

// ---------------------------------------------------------------------------
// xa = X @ lora_a  (raw fp32 math; X row stride = lda)
// ---------------------------------------------------------------------------
__global__ void lora_xa_kernel(const float* __restrict__ X, long lda,
                               const float* __restrict__ la,
                               float* __restrict__ xa)
{
    int s = blockIdx.x;
    int r = threadIdx.x & 15;
    int chunk = threadIdx.x >> 4;
    float sum = 0.f;
    int i0 = chunk * 256;
    const float* xr = X + (size_t)s * lda;
    for (int i = i0; i < i0 + 256; i++)
        sum += xr[i] * la[(size_t)i * RLORA + r];
    __shared__ float red[256];
    red[threadIdx.x] = sum;
    __syncthreads();
    for (int off = 128; off >= 16; off >>= 1) {
        if (threadIdx.x < off) red[threadIdx.x] += red[threadIdx.x + off];
        __syncthreads();
    }
    if (threadIdx.x < 16) xa[(size_t)s * RLORA + threadIdx.x] = red[threadIdx.x];
}

// ---------------------------------------------------------------------------
// V transpose: Vt[d_global][k] = V[k][d_global]   (4096 x 1024)
// ---------------------------------------------------------------------------
__global__ void vt_kernel(const float* __restrict__ V, float* __restrict__ Vt)
{
    __shared__ float tile[32][33];
    int x0 = blockIdx.x * 32;     // d (4096)
    int y0 = blockIdx.y * 32;     // k (1024)
    for (int i = threadIdx.y; i < 32; i += 8)
        tile[i][threadIdx.x] = V[(size_t)(y0 + i) * Hd + x0 + threadIdx.x];
    __syncthreads();
    for (int i = threadIdx.y; i < 32; i += 8)
        Vt[(size_t)(x0 + i) * Sq + y0 + threadIdx.x] = tile[threadIdx.x][i];
}

// ---------------------------------------------------------------------------
// GEMM, tile 128 x NT, K in 32-wide chunks.
// sm_103a cubin: tcgen05 tf32 SS MMA, cp.async double buffer, TMEM accum.
// generic cubin: FFMA smem-tiled fallback (correct, slower; not expected to
//                be selected on GB300 since an exact sm_103a cubin exists).
// MODE 0: C = D + bias[col]   MODE 1: C = D*scale + mask[row,col]   MODE 2: C = D
// ROUND: tf32-round the stored result.
// ---------------------------------------------------------------------------
template<int NT, int MODE, bool ROUND>
__global__ __launch_bounds__(256, 1)
void tf32_gemm(const float* __restrict__ A, long lda, long zA,
               const float* __restrict__ B, long ldb, long zB,
               float* __restrict__ C, long ldc, long zC,
               const float* __restrict__ aux, int CK)
{
#if TC_OK
    extern __shared__ char smem[];
    const unsigned sbase = smem_u32(smem);
    constexpr int ATILE = 128 * 128;           // bytes per A buffer
    constexpr int BTILE = NT * 128;            // bytes per B buffer
    constexpr unsigned ABUF0 = 1024;
    constexpr unsigned BBUF0 = 1024 + 2 * ATILE;
    constexpr uint32_t IDESC =
        (1u << 4) | (2u << 7) | (2u << 10) | ((NT / 8) << 17) | (8u << 24);

    const int tid = threadIdx.x, wid = tid >> 5, lane = tid & 31;
    const int bm = blockIdx.y * 128, bn = blockIdx.x * NT, bz = blockIdx.z;
    const float* Az = A + (size_t)zA * bz;
    const float* Bz = B + (size_t)zB * bz;
    float*       Cz = C + (size_t)zC * bz;

    if (wid == 0) TCGEN05_ALLOC(sbase, 256);
    if (tid == 0) { MBARRIER_INIT(sbase + 16, 1); MBARRIER_INIT(sbase + 24, 1); }
    __syncthreads();
    unsigned tmem;
    asm volatile("ld.shared.b32 %0, [%1];" : "=r"(tmem) : "r"(sbase));
    if (wid == 0) TCGEN05_RELINQUISH();

    bool isel = false;
    if (wid == 0) isel = elect_one();

    auto load_chunk = [&](int c) {
        int b = c & 1;
        unsigned sA = sbase + ABUF0 + b * ATILE;
        unsigned sB = sbase + BBUF0 + b * BTILE;
        const float* Ab = Az + (size_t)bm * lda + c * 32;
#pragma unroll
        for (int l = 0; l < 4; l++) {
            int s = tid + l * 256;
            int r = s >> 3, i = s & 7;
            cpa16(sA + swz(r * 128 + i * 16), Ab + (size_t)r * lda + i * 4);
        }
        const float* Bb = Bz + (size_t)bn * ldb + c * 32;
#pragma unroll
        for (int l = 0; l < NT / 32; l++) {
            int s = tid + l * 256;
            int r = s >> 3, i = s & 7;
            cpa16(sB + swz(r * 128 + i * 16), Bb + (size_t)r * ldb + i * 4);
        }
        asm volatile("cp.async.commit_group;" ::: "memory");
    };

    load_chunk(0);
    if (CK > 1) load_chunk(1);

    for (int c = 0; c < CK; ++c) {
        int b = c & 1;
        if (c + 1 < CK) asm volatile("cp.async.wait_group 1;" ::: "memory");
        else            asm volatile("cp.async.wait_group 0;" ::: "memory");
        __syncthreads();
        if (isel) {
            FENCE_PROXY_ASYNC();
            uint64_t ad = MAKE_SMEM_DESC(sbase + ABUF0 + b * ATILE);
            uint64_t bd = MAKE_SMEM_DESC(sbase + BBUF0 + b * BTILE);
#pragma unroll
            for (int s = 0; s < 4; s++)
                mma_tf32(tmem, ad + s * 2, bd + s * 2, IDESC,
                         (c > 0 || s > 0) ? 1u : 0u);
            TCGEN05_COMMIT(sbase + 16 + 8 * b);
        }
        if (c + 2 < CK) {
            MBARRIER_WAIT_PARITY(sbase + 16 + 8 * b, (c >> 1) & 1);
            load_chunk(c + 2);
        }
    }
    {   // final: wait all MMAs (last commit covers all prior)
        int c = CK - 1, b = c & 1;
        MBARRIER_WAIT_PARITY(sbase + 16 + 8 * b, (c >> 1) & 1);
    }
    TCGEN05_FENCE_AFTER();

    if (wid < 4) {
        int row = bm + wid * 32 + lane;
#pragma unroll
        for (int nb = 0; nb < NT / 32; nb++) {
            uint32_t r[32];
            TCGEN05_LD_32X32B_X32(r, tmem + nb * 32);
            TCGEN05_WAIT_LD();
            int col0 = bn + nb * 32;
            float v[32];
#pragma unroll
            for (int j = 0; j < 32; j++) {
                float d = __uint_as_float(r[j]);
                if (MODE == 0)      d += aux[col0 + j];
                else if (MODE == 1) d = d * 0.08838834764831845f
                                        + aux[(size_t)row * Sq + col0 + j];
                if (ROUND) d = tf32r(d);
                v[j] = d;
            }
            float4* dst = (float4*)(Cz + (size_t)row * ldc + col0);
#pragma unroll
            for (int q = 0; q < 8; q++)
                dst[q] = make_float4(v[4*q], v[4*q+1], v[4*q+2], v[4*q+3]);
        }
    }
    __syncthreads();
    if (wid == 0) TCGEN05_DEALLOC(tmem, 256);

#else  // ------- generic-arch FFMA fallback (correct, slower) -------------
    extern __shared__ char smem[];
    float* As = (float*)smem;                       // [16][128]
    float* Bs = (float*)(smem + 16 * 128 * 4);      // [16][NT]
    const int tid = threadIdx.x;
    const int bm = blockIdx.y * 128, bn = blockIdx.x * NT, bz = blockIdx.z;
    const float* Az = A + (size_t)zA * bz;
    const float* Bz = B + (size_t)zB * bz;
    float*       Cz = C + (size_t)zC * bz;
    const int Kd = CK * 32;
    const int tx = tid & 15, ty = tid >> 4;
    constexpr int JW = NT / 16;                     // 16 (NT=256) or 8 (NT=128)
    float acc[8][JW];
#pragma unroll
    for (int i = 0; i < 8; i++)
#pragma unroll
        for (int j = 0; j < JW; j++) acc[i][j] = 0.f;

    for (int k0 = 0; k0 < Kd; k0 += 16) {
#pragma unroll
        for (int l = 0; l < 2; l++) {               // A: 512 float4 slots
            int f = tid + l * 256;
            int r = f >> 2, c4 = f & 3;
            float4 v = *(const float4*)(Az + (size_t)(bm + r) * lda + k0 + c4 * 4);
            As[(c4 * 4 + 0) * 128 + r] = v.x; As[(c4 * 4 + 1) * 128 + r] = v.y;
            As[(c4 * 4 + 2) * 128 + r] = v.z; As[(c4 * 4 + 3) * 128 + r] = v.w;
        }
#pragma unroll
        for (int l = 0; l < NT / 64; l++) {         // B: NT*4 float4 slots
            int f = tid + l * 256;
            int r = f >> 2, c4 = f & 3;
            float4 v = *(const float4*)(Bz + (size_t)(bn + r) * ldb + k0 + c4 * 4);
            Bs[(c4 * 4 + 0) * NT + r] = v.x; Bs[(c4 * 4 + 1) * NT + r] = v.y;
            Bs[(c4 * 4 + 2) * NT + r] = v.z; Bs[(c4 * 4 + 3) * NT + r] = v.w;
        }
        __syncthreads();
#pragma unroll
        for (int kk = 0; kk < 16; kk++) {
            float ar[8], br[JW];
#pragma unroll
            for (int i = 0; i < 8; i++) ar[i] = As[kk * 128 + ty * 8 + i];
#pragma unroll
            for (int j = 0; j < JW; j++) br[j] = Bs[kk * NT + tx * JW + j];
#pragma unroll
            for (int i = 0; i < 8; i++)
#pragma unroll
                for (int j = 0; j < JW; j++)
                    acc[i][j] += ar[i] * br[j];
        }
        __syncthreads();
    }
#pragma unroll
    for (int i = 0; i < 8; i++) {
        int row = bm + ty * 8 + i;
#pragma unroll
        for (int j = 0; j < JW; j++) {
            int col = bn + tx * JW + j;
            float d = acc[i][j];
            if (MODE == 0)      d += aux[col];
            else if (MODE == 1) d = d * 0.08838834764831845f
                                    + aux[(size_t)row * Sq + col];
            if (ROUND) d = tf32r(d);
            Cz[(size_t)row * ldc + col] = d;
        }
    }
#endif
}

// ---------------------------------------------------------------------------
// Row softmax (1024 cols, in place), output tf32-rounded for the PV MMA.
// ---------------------------------------------------------------------------
__global__ void softmax_kernel(float* __restrict__ S)
{
    size_t row = blockIdx.x;
    float* p = S + row * Sq;
    int tid = threadIdx.x;
    __shared__ float red[256];
    float lmax = -3.4e38f;
    for (int i = tid; i < Sq; i += 256) lmax = fmaxf(lmax, p[i]);
    red[tid] = lmax; __syncthreads();
    for (int off = 128; off > 0; off >>= 1) {
        if (tid < off) red[tid] = fmaxf(red[tid], red[tid + off]);
        __syncthreads();
    }
    float m = red[0]; __syncthreads();
    float lsum = 0.f;
    for (int i = tid; i < Sq; i += 256) {
        float e = expf(p[i] - m);
        p[i] = e;
        lsum += e;
    }
    red[tid] = lsum; __syncthreads();
    for (int off = 128; off > 0; off >>= 1) {
        if (tid < off) red[tid] += red[tid + off];
        __syncthreads();
    }
    float inv = 1.0f / red[0];
    for (int i = tid; i < Sq; i += 256) p[i] = tf32r(p[i] * inv);
}

// ---------------------------------------------------------------------------
// Exact rank-k selection (3-pass radix on float bits; data nonneg after abs).
// Supports strided rows: flat index i -> data[(i>>rlog)*lda + (i & rmask)].
// ---------------------------------------------------------------------------
__global__ void sel_init(unsigned long long k)
{
    int t = blockIdx.x * blockDim.x + threadIdx.x;
    if (t < 2048) g_hist[t] = 0;
    if (t == 0) { g_ksel = k; g_prefix = 0u; }
}

__global__ void sel_hist(const float* __restrict__ data, size_t n,
                         int rlog, long lda,
                         unsigned mask, int shift, int bits)
{
    __shared__ unsigned sh[2048];
    for (int i = threadIdx.x; i < 2048; i += blockDim.x) sh[i] = 0;
    __syncthreads();
    unsigned pref = g_prefix;
    unsigned nb = (1u << bits) - 1u;
    size_t rmask = ((size_t)1 << rlog) - 1;
    size_t stride = (size_t)gridDim.x * blockDim.x;
    unsigned zc = 0;
    for (size_t i = (size_t)blockIdx.x * blockDim.x + threadIdx.x; i < n; i += stride) {
        size_t pos = (i >> rlog) * (size_t)lda + (i & rmask);
        unsigned u = __float_as_uint(data[pos]) & 0x7FFFFFFFu;
        if ((u & mask) == pref) {
            if (u == 0u) zc++;                      // heavy zero mass (softmax)
            else atomicAdd(&sh[(u >> shift) & nb], 1u);
        }
    }
    if (zc) atomicAdd(&sh[0], zc);
    __syncthreads();
    for (int i = threadIdx.x; i < (1 << bits); i += blockDim.x)
        if (sh[i]) atomicAdd(&g_hist[i], sh[i]);
}

__global__ void sel_pick(int shift, float* out)
{
    __shared__ unsigned h[2048];
    for (int i = threadIdx.x; i < 2048; i += blockDim.x) {
        h[i] = g_hist[i];
        g_hist[i] = 0;
    }
    __syncthreads();
    if (threadIdx.x == 0) {
        unsigned long long k = g_ksel;
        unsigned long long cum = 0;
        int sel = 0;
        for (int b = 0; b < 2048; b++) {
            if (cum + h[b] >= k) { sel = b; break; }
            cum += h[b];
        }
        g_ksel = k - cum;
        unsigned pref = g_prefix | ((unsigned)sel << shift);
        g_prefix = pref;
        if (out) *out = __uint_as_float(pref);
    }
}

static void run_select(const float* data, size_t n, int rlog, long lda,
                       unsigned long long k, float* out)
{
    sel_init<<<2, 1024>>>(k);
    sel_hist<<<1024, 256>>>(data, n, rlog, lda, 0u,          21, 11);
    sel_pick<<<1, 1024>>>(21, nullptr);
    sel_hist<<<1024, 256>>>(data, n, rlog, lda, 0xFFE00000u, 10, 11);
    sel_pick<<<1, 1024>>>(10, nullptr);
    sel_hist<<<1024, 256>>>(data, n, rlog, lda, 0xFFFFFC00u,  0, 10);
    sel_pick<<<1, 1024>>>(0, out);
}

// ---------------------------------------------------------------------------
// Host orchestration
// ---------------------------------------------------------------------------
extern "C" void kernel_launch(void* const* d_in, const int* in_sizes, int n_in,
                              void* d_out, int out_size)
{
    const float* x    = (const float*)d_in[0];
    const int*   codes[4];
    const float *amax[4], *bias[4], *la[4], *lb[4];
    for (int p = 0; p < 4; p++) {
        codes[p] = (const int*)  d_in[1 + p * 5 + 0];
        amax[p]  = (const float*)d_in[1 + p * 5 + 1];
        bias[p]  = (const float*)d_in[1 + p * 5 + 2];
        la[p]    = (const float*)d_in[1 + p * 5 + 3];
        lb[p]    = (const float*)d_in[1 + p * 5 + 4];
    }
    const float* mask = (const float*)d_in[21];
    float* out = (float*)d_out;

    float *pAa, *pBa, *pQ, *pK, *pV, *pVt, *pAttn, *pXa;
    cudaGetSymbolAddress((void**)&pAa,   g_Aaug);
    cudaGetSymbolAddress((void**)&pBa,   g_Baug);
    cudaGetSymbolAddress((void**)&pQ,    g_q);
    cudaGetSymbolAddress((void**)&pK,    g_k);
    cudaGetSymbolAddress((void**)&pV,    g_v);
    cudaGetSymbolAddress((void**)&pVt,   g_vt);
    cudaGetSymbolAddress((void**)&pAttn, g_attn);
    cudaGetSymbolAddress((void**)&pXa,   g_xa);

    // dynamic smem opt-in (idempotent)
    const int SM256 = 1024 + 2 * (128 * 128) + 2 * (256 * 128);  // 99328
    const int SM128 = 1024 + 2 * (128 * 128) + 2 * (128 * 128);  // 66560
    cudaFuncSetAttribute(tf32_gemm<256, 0, true>,
        cudaFuncAttributeMaxDynamicSharedMemorySize, SM256);
    cudaFuncSetAttribute(tf32_gemm<256, 0, false>,
        cudaFuncAttributeMaxDynamicSharedMemorySize, SM256);
    cudaFuncSetAttribute(tf32_gemm<256, 1, false>,
        cudaFuncAttributeMaxDynamicSharedMemorySize, SM256);
    cudaFuncSetAttribute(tf32_gemm<128, 2, true>,
        cudaFuncAttributeMaxDynamicSharedMemorySize, SM128);

    const int CKP = KAUG / 32;      // 129 chunks for projections

    // --- A_aug <- rounded x ---
    roundx_kernel<<<NELEM / 4 / 256, 256>>>(x, pAa);

    // --- Q, K, V projections ---
    float* qkv[3] = { pQ, pK, pV };
    for (int p = 0; p < 3; p++) {
        dequant_kernel<<<WELEM / 16 / 256, 256>>>(codes[p], amax[p], pBa);
        tailB_kernel<<<Hd, 32>>>(lb[p], pBa);
        lora_xa_kernel<<<Sq, 256>>>(x, Hd, la[p], pXa);
        tailA_kernel<<<Sq, 32>>>(pXa, pAa);
        tf32_gemm<256, 0, true><<<dim3(16, 8, 1), 256, SM256>>>(
            pAa, KAUG, 0, pBa, KAUG, 0, qkv[p], Hd, 0, bias[p], CKP);
    }

    // --- Attention ---
    tf32_gemm<256, 1, false><<<dim3(4, 8, NHEAD), 256, SM256>>>(
        pQ, Hd, HDIM, pK, Hd, HDIM, pAttn, Sq, (long)Sq * Sq, mask, HDIM / 32);
    softmax_kernel<<<NHEAD * Sq, 256>>>(pAttn);
    vt_kernel<<<dim3(Hd / 32, Sq / 32), dim3(32, 8)>>>(pV, pVt);
    // PV writes the attention output directly into A_aug (stride KAUG)
    tf32_gemm<128, 2, true><<<dim3(1, 8, NHEAD), 256, SM128>>>(
        pAttn, Sq, (long)Sq * Sq, pVt, Sq, (long)HDIM * Sq,
        pAa, KAUG, HDIM, nullptr, Sq / 32);

    // --- Output projection -> d_out ---
    dequant_kernel<<<WELEM / 16 / 256, 256>>>(codes[3], amax[3], pBa);
    tailB_kernel<<<Hd, 32>>>(lb[3], pBa);
    lora_xa_kernel<<<Sq, 256>>>(pAa, KAUG, la[3], pXa);
    tailA_kernel<<<Sq, 32>>>(pXa, pAa);
    tf32_gemm<256, 0, false><<<dim3(16, 8, 1), 256, SM256>>>(
        pAa, KAUG, 0, pBa, KAUG, 0, out, Hd, 0, bias[3], CKP);

    // --- kth values: [x, qh, kh, vh, a, o] ---
    const unsigned long long kN = NELEM / 2;
    const unsigned long long kA = AELEM / 2;
    run_select(x,     NELEM, 12, Hd,   kN, out + NELEM + 0);
    run_select(pQ,    NELEM, 12, Hd,   kN, out + NELEM + 1);
    run_select(pK,    NELEM, 12, Hd,   kN, out + NELEM + 2);
    run_select(pV,    NELEM, 12, Hd,   kN, out + NELEM + 3);
    run_select(pAttn, AELEM, 10, Sq,   kA, out + NELEM + 4);
    run_select(pAa,   NELEM, 12, KAUG, kN, out + NELEM + 5);
}

// round 4
// speedup vs baseline: 4.1382x; 1.0708x over previous
#include <cuda_runtime.h>
#include <cstdint>
#include <cstddef>

// ---------------------------------------------------------------------------
// Problem constants
// ---------------------------------------------------------------------------
#define Sq      1024
#define Hd      4096
#define NHEAD   32
#define HDIM    128
#define RLORA   16
#define NELEM   (Sq * Hd)                   // 4194304
#define WELEM   (Hd * Hd)                   // 16777216
#define AELEM   ((size_t)NHEAD * Sq * Sq)   // 33554432
#define KAUG    4160                        // 4096 + 64 pad (lora 16 + zeros) = 65*64

// Arch-specific (sm_103a) feature gate: tcgen05 only exists in the
// arch-specific compilation pass. The generic compute_103 pass gets an
// FFMA fallback body so every embedded cubin/PTX is valid AND correct.
#if defined(__CUDA_ARCH_FEAT_SM103_ALL) || defined(__CUDA_ARCH_FEAT_SM100_ALL) || \
    defined(__CUDA_ARCH_FEAT_SM101_ALL)
#define TC_OK 1
#else
#define TC_OK 0
#endif

// ---------------------------------------------------------------------------
// Device scratch (static: no allocation allowed)
// ---------------------------------------------------------------------------
__device__ float g_Aaug[Sq * KAUG];           // [1024,4160] rounded A (x, later o)
__device__ float g_Baug[Hd * KAUG];           // [4096,4160] dequant W + lb^T tail
__device__ float g_q[NELEM];
__device__ float g_k[NELEM];
__device__ float g_v[NELEM];
__device__ float g_vt[NELEM];                 // V transposed: [4096 d][1024 k]
__device__ float g_attn[AELEM];               // scores -> probs (tf32-rounded)
__device__ float g_xa[Sq * RLORA];            // x @ lora_a

// selection state
__device__ unsigned long long g_ksel;
__device__ unsigned           g_prefix;
__device__ unsigned           g_hist[2048];

__constant__ float c_nf4[16] = {
    -1.0f, -0.6961928009986877f, -0.5250730514526367f, -0.39491748809814453f,
    -0.28444138169288635f, -0.18477343022823334f, -0.09105003625154495f, 0.0f,
    0.07958029955625534f, 0.16093020141124725f, 0.24611230194568634f,
    0.33791524171829224f, 0.4407098591327667f, 0.5626170039176941f,
    0.7229568362236023f, 1.0f };

// ---------------------------------------------------------------------------
// PTX helpers
// ---------------------------------------------------------------------------
__device__ __forceinline__ uint32_t smem_u32(const void* p) {
    uint32_t a;
    asm("{ .reg .u64 t; cvta.to.shared.u64 t, %1; cvt.u32.u64 %0, t; }"
        : "=r"(a) : "l"(p));
    return a;
}
__device__ __forceinline__ bool elect_one() {
    uint32_t pred;
    asm volatile("{\n\t.reg .pred p;\n\telect.sync _|p, 0xFFFFFFFF;\n\t"
                 "selp.b32 %0, 1, 0, p;\n\t}" : "=r"(pred));
    return pred != 0;
}
__device__ __forceinline__ float tf32r(float v) {
    unsigned u;
    asm("cvt.rna.tf32.f32 %0, %1;" : "=r"(u) : "f"(v));
    return __uint_as_float(u);
}
__device__ __forceinline__ unsigned swz(unsigned off) {   // SW128 swizzle
    return off ^ ((off >> 3) & 0x70);
}
__device__ __forceinline__ void cpa16(unsigned dst, const void* src) {
    asm volatile("cp.async.cg.shared.global [%0], [%1], 16;"
                 :: "r"(dst), "l"(src));
}

static constexpr uint64_t SMEM_DESC_BASE_SW128 =
    (uint64_t(2)  << 61) | (uint64_t(1) << 46) |
    (uint64_t(64) << 32) | (uint64_t(1) << 16);
#define MAKE_SMEM_DESC(base_addr) \
    (SMEM_DESC_BASE_SW128 | ((uint64_t)((base_addr) >> 4) & 0x3FFF))

#define MBARRIER_INIT(mbar, count) \
    asm volatile("mbarrier.init.shared.b64 [%0], %1;" \
        :: "r"((uint32_t)(mbar)), "r"((uint32_t)(count)) : "memory")
#define MBARRIER_WAIT_PARITY(mbar_smem_addr, phase_parity) do { \
    uint32_t _mbar = (uint32_t)(mbar_smem_addr); \
    uint32_t _parity = (uint32_t)(phase_parity); \
    uint32_t _done; \
    asm volatile("{\n\t.reg .pred p;\n\t" \
        "mbarrier.try_wait.parity.acquire.cta.shared::cta.b64 p, [%1], %2;\n\t" \
        "selp.b32 %0, 1, 0, p;\n\t}" \
        : "=r"(_done) : "r"(_mbar), "r"(_parity) : "memory"); \
    if (!_done) { \
        asm volatile("{\n\t.reg .pred P1;\n\t" \
            "WAIT_LOOP_%=:\n\t" \
            "mbarrier.try_wait.parity.acquire.cta.shared::cta.b64 P1, [%0], %1, 0x989680;\n\t" \
            "@P1 bra.uni WAIT_DONE_%=;\n\t" \
            "bra.uni WAIT_LOOP_%=;\n\t" \
            "WAIT_DONE_%=:\n\t}" \
            :: "r"(_mbar), "r"(_parity) : "memory"); \
    } \
} while (0)

#if TC_OK
#define TCGEN05_ALLOC(smem_result_addr, nCols) \
    asm volatile("tcgen05.alloc.cta_group::1.sync.aligned.shared::cta.b32 [%0], %1;" \
        :: "r"((uint32_t)(smem_result_addr)), "r"((uint32_t)(nCols)) : "memory")
#define TCGEN05_DEALLOC(tmem_addr, nCols) \
    asm volatile("tcgen05.dealloc.cta_group::1.sync.aligned.b32 %0, %1;" \
        :: "r"(tmem_addr), "r"((uint32_t)(nCols)))
#define TCGEN05_RELINQUISH() \
    asm volatile("tcgen05.relinquish_alloc_permit.cta_group::1.sync.aligned;")
#define TCGEN05_COMMIT(mbar) \
    asm volatile("tcgen05.commit.cta_group::1.mbarrier::arrive::one.shared::cluster.b64 [%0];" \
        :: "r"((uint32_t)(mbar)) : "memory")
#define TCGEN05_FENCE_AFTER() \
    asm volatile("tcgen05.fence::after_thread_sync;" ::: "memory")
#define TCGEN05_WAIT_LD() \
    asm volatile("tcgen05.wait::ld.sync.aligned;" ::: "memory")
#define FENCE_PROXY_ASYNC() \
    asm volatile("fence.proxy.async.shared::cta;" ::: "memory")

#define TCGEN05_LD_32X32B_X32(r, tmem_addr) \
    asm volatile( \
        "tcgen05.ld.sync.aligned.32x32b.x32.b32 " \
        "{%0, %1, %2, %3, %4, %5, %6, %7, " \
        " %8, %9, %10, %11, %12, %13, %14, %15, " \
        " %16, %17, %18, %19, %20, %21, %22, %23, " \
        " %24, %25, %26, %27, %28, %29, %30, %31}, [%32];" \
        : "=r"((r)[0]),  "=r"((r)[1]),  "=r"((r)[2]),  "=r"((r)[3]), \
          "=r"((r)[4]),  "=r"((r)[5]),  "=r"((r)[6]),  "=r"((r)[7]), \
          "=r"((r)[8]),  "=r"((r)[9]),  "=r"((r)[10]), "=r"((r)[11]), \
          "=r"((r)[12]), "=r"((r)[13]), "=r"((r)[14]), "=r"((r)[15]), \
          "=r"((r)[16]), "=r"((r)[17]), "=r"((r)[18]), "=r"((r)[19]), \
          "=r"((r)[20]), "=r"((r)[21]), "=r"((r)[22]), "=r"((r)[23]), \
          "=r"((r)[24]), "=r"((r)[25]), "=r"((r)[26]), "=r"((r)[27]), \
          "=r"((r)[28]), "=r"((r)[29]), "=r"((r)[30]), "=r"((r)[31]) \
        : "r"(tmem_addr))

__device__ __forceinline__ void mma_tf32(uint32_t d, uint64_t ad, uint64_t bd,
                                         uint32_t idesc, uint32_t en)
{
    asm volatile(
        "{\n\t"
        ".reg .pred p;\n\t"
        "setp.ne.u32 p, %5, 0;\n\t"
        "tcgen05.mma.cta_group::1.kind::tf32 [%0], %1, %2, %3, {%4, %4, %4, %4}, p;\n\t"
        "}"
        :: "r"(d), "l"(ad), "l"(bd), "r"(idesc), "r"(0u), "r"(en)
        : "memory");
}
#endif // TC_OK

// ---------------------------------------------------------------------------
// NF4 dequant -> B_aug (stride KAUG), tf32-rounded. 16 elems/thread.
// ---------------------------------------------------------------------------
__global__ void dequant_kernel(const int* __restrict__ codes,
                               const float* __restrict__ absmax,
                               float* __restrict__ W)
{
    size_t t = (size_t)blockIdx.x * blockDim.x + threadIdx.x;
    size_t base = t * 16;
    if (base >= (size_t)WELEM) return;
    float am = absmax[base >> 6];            // 16 consecutive share one block
    size_t row = base >> 12, col = base & 4095;
    float* dst = W + row * KAUG + col;
#pragma unroll
    for (int q = 0; q < 4; q++) {
        int4 c = *(const int4*)(codes + base + q * 4);
        float4 o;
        o.x = tf32r(c_nf4[c.x & 15] * am);
        o.y = tf32r(c_nf4[c.y & 15] * am);
        o.z = tf32r(c_nf4[c.z & 15] * am);
        o.w = tf32r(c_nf4[c.w & 15] * am);
        *(float4*)(dst + q * 4) = o;
    }
}

// ---------------------------------------------------------------------------
// Round x (fp32 -> tf32) into A_aug [1024, KAUG]
// ---------------------------------------------------------------------------
__global__ void roundx_kernel(const float* __restrict__ x, float* __restrict__ Aa)
{
    size_t t = (size_t)blockIdx.x * blockDim.x + threadIdx.x;
    size_t base = t * 4;
    if (base >= (size_t)NELEM) return;
    float4 v = *(const float4*)(x + base);
    float4 o = make_float4(tf32r(v.x), tf32r(v.y), tf32r(v.z), tf32r(v.w));
    size_t row = base >> 12, col = base & 4095;
    *(float4*)(Aa + row * KAUG + col) = o;
}

// A_aug lora tail: cols 4096..4159 <- xa (tf32) | zeros
__global__ void tailA_kernel(const float* __restrict__ xa, float* __restrict__ Aa)
{
    int row = blockIdx.x, r = threadIdx.x;       // 64 threads
    float v = (r < RLORA) ? tf32r(xa[row * RLORA + r]) : 0.f;
    Aa[(size_t)row * KAUG + 4096 + r] = v;
}
// B_aug lora tail: cols 4096..4159 <- lb^T (tf32) | zeros
__global__ void tailB_kernel(const float* __restrict__ lb, float* __restrict__ Ba)
{
    int n = blockIdx.x, r = threadIdx.x;         // 64 threads
    float v = (r < RLORA) ? tf32r(lb[(size_t)r * Hd + n]) : 0.f;
    Ba[(size_t)n * KAUG + 4096 + r] = v;
}

// ---------------------------------------------------------------------------
// xa = X @ lora_a  (fp32; X row stride = lda). 4 accumulator chains for MLP.
// ---------------------------------------------------------------------------
__global__ void lora_xa_kernel(const float* __restrict__ X, long lda,
                               const float* __restrict__ la,
                               float* __restrict__ xa)
{
    int s = blockIdx.x;
    int r = threadIdx.x & 15;
    int chunk = threadIdx.x >> 4;
    const float* xr = X + (size_t)s * lda + chunk * 256;
    const float* lp = la + (size_t)(chunk * 256) * RLORA + r;
    float a0 = 0.f, a1 = 0.f, a2 = 0.f, a3 = 0.f;
#pragma unroll 8
    for (int i = 0; i < 256; i += 4) {
        a0 += xr[i + 0] * lp[(i + 0) * RLORA];
        a1 += xr[i + 1] * lp[(i + 1) * RLORA];
        a2 += xr[i + 2] * lp[(i + 2) * RLORA];
        a3 += xr[i + 3] * lp[(i + 3) * RLORA];
    }
    float sum = (a0 + a1) + (a2 + a3);
    __shared__ float red[256];
    red[threadIdx.x] = sum;
    __syncthreads();
    for (int off = 128; off >= 16; off >>= 1) {
        if (threadIdx.x < off) red[threadIdx.x] += red[threadIdx.x + off];
        __syncthreads();
    }
    if (threadIdx.x < 16) xa[(size_t)s * RLORA + threadIdx.x] = red[threadIdx.x];
}

// ---------------------------------------------------------------------------
// V transpose: Vt[d_global][k] = V[k][d_global]   (4096 x 1024)
// ---------------------------------------------------------------------------
__global__ void vt_kernel(const float* __restrict__ V, float* __restrict__ Vt)
{
    __shared__ float tile[32][33];
    int x0 = blockIdx.x * 32;     // d (4096)
    int y0 = blockIdx.y * 32;     // k (1024)
    for (int i = threadIdx.y; i < 32; i += 8)
        tile[i][threadIdx.x] = V[(size_t)(y0 + i) * Hd + x0 + threadIdx.x];
    __syncthreads();
    for (int i = threadIdx.y; i < 32; i += 8)
        Vt[(size_t)(x0 + i) * Sq + y0 + threadIdx.x] = tile[threadIdx.x][i];
}

// ---------------------------------------------------------------------------
// GEMM, tile 128 x NT, K consumed in 64-wide chunks (2 sub-tiles of 32 cols,
// 8 tcgen05 dispatches of K=8 per chunk). Double-buffered cp.async.
// MODE 0: C = D + bias[col]   MODE 1: C = D*scale + mask[row,col]   MODE 2: C = D
// ROUND: tf32-round the stored result.  CK = number of 64-chunks (>= 2).
// ---------------------------------------------------------------------------
template<int NT, int MODE, bool ROUND>
__global__ __launch_bounds__(256, 1)
void tf32_gemm(const float* __restrict__ A, long lda, long zA,
               const float* __restrict__ B, long ldb, long zB,
               float* __restrict__ C, long ldc, long zC,
               const float* __restrict__ aux, int CK)
{
#if TC_OK
    extern __shared__ char smem[];
    const unsigned sbase = smem_u32(smem);
    constexpr int ASUB = 128 * 128;            // 16KB per 32-col sub-tile
    constexpr int BSUB = NT * 128;             // 32KB (NT=256) / 16KB (NT=128)
    constexpr int ABUF = 2 * ASUB;             // per-buffer A bytes
    constexpr int BBUF = 2 * BSUB;             // per-buffer B bytes
    constexpr unsigned ABUF0 = 1024;
    constexpr unsigned BBUF0 = 1024 + 2 * ABUF;
    constexpr uint32_t IDESC =
        (1u << 4) | (2u << 7) | (2u << 10) | ((NT / 8) << 17) | (8u << 24);

    const int tid = threadIdx.x, wid = tid >> 5, lane = tid & 31;
    const int bm = blockIdx.y * 128, bn = blockIdx.x * NT, bz = blockIdx.z;
    const float* Az = A + (size_t)zA * bz;
    const float* Bz = B + (size_t)zB * bz;
    float*       Cz = C + (size_t)zC * bz;

    if (wid == 0) TCGEN05_ALLOC(sbase, 256);
    if (tid == 0) { MBARRIER_INIT(sbase + 16, 1); MBARRIER_INIT(sbase + 24, 1); }
    __syncthreads();
    unsigned tmem;
    asm volatile("ld.shared.b32 %0, [%1];" : "=r"(tmem) : "r"(sbase));
    if (wid == 0) TCGEN05_RELINQUISH();

    bool isel = false;
    if (wid == 0) isel = elect_one();

    auto load_chunk = [&](int c) {
        int b = c & 1;
        unsigned sA = sbase + ABUF0 + b * ABUF;
        unsigned sB = sbase + BBUF0 + b * BBUF;
        const float* Ab = Az + (size_t)bm * lda + c * 64;
#pragma unroll
        for (int l = 0; l < 8; l++) {                  // 2048 float4 for A
            int s = tid + l * 256;
            int sub = s >> 10, w = s & 1023;
            int r = w >> 3, i = w & 7;
            cpa16(sA + sub * ASUB + swz(r * 128 + i * 16),
                  Ab + (size_t)r * lda + sub * 32 + i * 4);
        }
        const float* Bb = Bz + (size_t)bn * ldb + c * 64;
#pragma unroll
        for (int l = 0; l < NT / 16; l++) {            // NT*16 float4 for B
            int s = tid + l * 256;
            int sub = s / (NT * 8), w = s % (NT * 8);
            int r = w >> 3, i = w & 7;
            cpa16(sB + sub * BSUB + swz(r * 128 + i * 16),
                  Bb + (size_t)r * ldb + sub * 32 + i * 4);
        }
        asm volatile("cp.async.commit_group;" ::: "memory");
    };

    load_chunk(0);
    load_chunk(1);

    for (int c = 0; c < CK; ++c) {
        int b = c & 1;
        if (c + 1 < CK) asm volatile("cp.async.wait_group 1;" ::: "memory");
        else            asm volatile("cp.async.wait_group 0;" ::: "memory");
        __syncthreads();
        if (isel) {
            FENCE_PROXY_ASYNC();
#pragma unroll
            for (int j = 0; j < 2; j++) {
                uint64_t ad = MAKE_SMEM_DESC(sbase + ABUF0 + b * ABUF + j * ASUB);
                uint64_t bd = MAKE_SMEM_DESC(sbase + BBUF0 + b * BBUF + j * BSUB);
#pragma unroll
                for (int s = 0; s < 4; s++)
                    mma_tf32(tmem, ad + s * 2, bd + s * 2, IDESC,
                             (c > 0 || j > 0 || s > 0) ? 1u : 0u);
            }
            TCGEN05_COMMIT(sbase + 16 + 8 * b);
        }
        if (c + 2 < CK) {
            MBARRIER_WAIT_PARITY(sbase + 16 + 8 * b, (c >> 1) & 1);
            load_chunk(c + 2);
        }
    }
    {   // final: wait all MMAs (last commit covers all prior)
        int c = CK - 1, b = c & 1;
        MBARRIER_WAIT_PARITY(sbase + 16 + 8 * b, (c >> 1) & 1);
    }
    TCGEN05_FENCE_AFTER();

    if (wid < 4) {
        int row = bm + wid * 32 + lane;
#pragma unroll
        for (int nb = 0; nb < NT / 32; nb++) {
            uint32_t r[32];
            TCGEN05_LD_32X32B_X32(r, tmem + nb * 32);
            TCGEN05_WAIT_LD();
            int col0 = bn + nb * 32;
            float v[32];
#pragma unroll
            for (int j = 0; j < 32; j++) {
                float d = __uint_as_float(r[j]);
                if (MODE == 0)      d += aux[col0 + j];
                else if (MODE == 1) d = d * 0.08838834764831845f
                                        + aux[(size_t)row * Sq + col0 + j];
                if (ROUND) d = tf32r(d);
                v[j] = d;
            }
            float4* dst = (float4*)(Cz + (size_t)row * ldc + col0);
#pragma unroll
            for (int q = 0; q < 8; q++)
                dst[q] = make_float4(v[4*q], v[4*q+1], v[4*q+2], v[4*q+3]);
        }
    }
    __syncthreads();
    if (wid == 0) TCGEN05_DEALLOC(tmem, 256);

#else  // ------- generic-arch FFMA fallback (correct, slower) -------------
    extern __shared__ char smem[];
    float* As = (float*)smem;                       // [16][128]
    float* Bs = (float*)(smem + 16 * 128 * 4);      // [16][NT]
    const int tid = threadIdx.x;
    const int bm = blockIdx.y * 128, bn = blockIdx.x * NT, bz = blockIdx.z;
    const float* Az = A + (size_t)zA * bz;
    const float* Bz = B + (size_t)zB * bz;
    float*       Cz = C + (size_t)zC * bz;
    const int Kd = CK * 64;
    const int tx = tid & 15, ty = tid >> 4;
    constexpr int JW = NT / 16;
    float acc[8][JW];
#pragma unroll
    for (int i = 0; i < 8; i++)
#pragma unroll
        for (int j = 0; j < JW; j++) acc[i][j] = 0.f;

    for (int k0 = 0; k0 < Kd; k0 += 16) {
#pragma unroll
        for (int l = 0; l < 2; l++) {
            int f = tid + l * 256;
            int r = f >> 2, c4 = f & 3;
            float4 v = *(const float4*)(Az + (size_t)(bm + r) * lda + k0 + c4 * 4);
            As[(c4 * 4 + 0) * 128 + r] = v.x; As[(c4 * 4 + 1) * 128 + r] = v.y;
            As[(c4 * 4 + 2) * 128 + r] = v.z; As[(c4 * 4 + 3) * 128 + r] = v.w;
        }
#pragma unroll
        for (int l = 0; l < NT / 64; l++) {
            int f = tid + l * 256;
            int r = f >> 2, c4 = f & 3;
            float4 v = *(const float4*)(Bz + (size_t)(bn + r) * ldb + k0 + c4 * 4);
            Bs[(c4 * 4 + 0) * NT + r] = v.x; Bs[(c4 * 4 + 1) * NT + r] = v.y;
            Bs[(c4 * 4 + 2) * NT + r] = v.z; Bs[(c4 * 4 + 3) * NT + r] = v.w;
        }
        __syncthreads();
#pragma unroll
        for (int kk = 0; kk < 16; kk++) {
            float ar[8], br[JW];
#pragma unroll
            for (int i = 0; i < 8; i++) ar[i] = As[kk * 128 + ty * 8 + i];
#pragma unroll
            for (int j = 0; j < JW; j++) br[j] = Bs[kk * NT + tx * JW + j];
#pragma unroll
            for (int i = 0; i < 8; i++)
#pragma unroll
                for (int j = 0; j < JW; j++)
                    acc[i][j] += ar[i] * br[j];
        }
        __syncthreads();
    }
#pragma unroll
    for (int i = 0; i < 8; i++) {
        int row = bm + ty * 8 + i;
#pragma unroll
        for (int j = 0; j < JW; j++) {
            int col = bn + tx * JW + j;
            float d = acc[i][j];
            if (MODE == 0)      d += aux[col];
            else if (MODE == 1) d = d * 0.08838834764831845f
                                    + aux[(size_t)row * Sq + col];
            if (ROUND) d = tf32r(d);
            Cz[(size_t)row * ldc + col] = d;
        }
    }
#endif
}

// ---------------------------------------------------------------------------
// Single-pass row softmax (1024 cols, in place): one float4 per thread,
// shuffle+smem reductions, one read + one write. Output tf32-rounded.
// ---------------------------------------------------------------------------
__global__ void softmax_kernel(float* __restrict__ S)
{
    size_t row = blockIdx.x;
    float4* p = (float4*)(S + row * Sq);
    int tid = threadIdx.x;                  // 256
    float4 v = p[tid];
    __shared__ float red[8];

    float m = fmaxf(fmaxf(v.x, v.y), fmaxf(v.z, v.w));
#pragma unroll
    for (int o = 16; o > 0; o >>= 1) m = fmaxf(m, __shfl_xor_sync(~0u, m, o));
    if ((tid & 31) == 0) red[tid >> 5] = m;
    __syncthreads();
    m = red[0];
#pragma unroll
    for (int w = 1; w < 8; w++) m = fmaxf(m, red[w]);
    __syncthreads();

    float4 e;
    e.x = expf(v.x - m); e.y = expf(v.y - m);
    e.z = expf(v.z - m); e.w = expf(v.w - m);
    float s = (e.x + e.y) + (e.z + e.w);
#pragma unroll
    for (int o = 16; o > 0; o >>= 1) s += __shfl_xor_sync(~0u, s, o);
    if ((tid & 31) == 0) red[tid >> 5] = s;
    __syncthreads();
    s = red[0];
#pragma unroll
    for (int w = 1; w < 8; w++) s += red[w];
    float inv = 1.0f / s;
    p[tid] = make_float4(tf32r(e.x * inv), tf32r(e.y * inv),
                         tf32r(e.z * inv), tf32r(e.w * inv));
}

// ---------------------------------------------------------------------------
// Exact rank-k selection (3-pass radix on float bits; data nonneg after abs).
// Supports strided rows: flat index i -> data[(i>>rlog)*lda + (i & rmask)].
// ---------------------------------------------------------------------------
__global__ void sel_init(unsigned long long k)
{
    int t = blockIdx.x * blockDim.x + threadIdx.x;
    if (t < 2048) g_hist[t] = 0;
    if (t == 0) { g_ksel = k; g_prefix = 0u; }
}

__global__ void sel_hist(const float* __restrict__ data, size_t n,
                         int rlog, long lda,
                         unsigned mask, int shift, int bits)
{
    __shared__ unsigned sh[2048];
    for (int i = threadIdx.x; i < 2048; i += blockDim.x) sh[i] = 0;
    __syncthreads();
    unsigned pref = g_prefix;
    unsigned nb = (1u << bits) - 1u;
    size_t rmask = ((size_t)1 << rlog) - 1;
    size_t stride = (size_t)gridDim.x * blockDim.x;
    unsigned zc = 0;
    for (size_t i = (size_t)blockIdx.x * blockDim.x + threadIdx.x; i < n; i += stride) {
        size_t pos = (i >> rlog) * (size_t)lda + (i & rmask);
        unsigned u = __float_as_uint(data[pos]) & 0x7FFFFFFFu;
        if ((u & mask) == pref) {
            if (u == 0u) zc++;                      // heavy zero mass (softmax)
            else atomicAdd(&sh[(u >> shift) & nb], 1u);
        }
    }
    if (zc) atomicAdd(&sh[0], zc);
    __syncthreads();
    for (int i = threadIdx.x; i < (1 << bits); i += blockDim.x)
        if (sh[i]) atomicAdd(&g_hist[i], sh[i]);
}

__global__ void sel_pick(int shift, float* out)
{
    __shared__ unsigned h[2048];
    for (int i = threadIdx.x; i < 2048; i += blockDim.x) {
        h[i] = g_hist[i];
        g_hist[i] = 0;
    }
    __syncthreads();
    if (threadIdx.x == 0) {
        unsigned long long k = g_ksel;
        unsigned long long cum = 0;
        int sel = 0;
        for (int b = 0; b < 2048; b++) {
            if (cum + h[b] >= k) { sel = b; break; }
            cum += h[b];
        }
        g_ksel = k - cum;
        unsigned pref = g_prefix | ((unsigned)sel << shift);
        g_prefix = pref;
        if (out) *out = __uint_as_float(pref);
    }
}

static void run_select(const float* data, size_t n, int rlog, long lda,
                       unsigned long long k, float* out)
{
    sel_init<<<2, 1024>>>(k);
    sel_hist<<<1024, 256>>>(data, n, rlog, lda, 0u,          21, 11);
    sel_pick<<<1, 1024>>>(21, nullptr);
    sel_hist<<<1024, 256>>>(data, n, rlog, lda, 0xFFE00000u, 10, 11);
    sel_pick<<<1, 1024>>>(10, nullptr);
    sel_hist<<<1024, 256>>>(data, n, rlog, lda, 0xFFFFFC00u,  0, 10);
    sel_pick<<<1, 1024>>>(0, out);
}

// ---------------------------------------------------------------------------
// Host orchestration
// ---------------------------------------------------------------------------
extern "C" void kernel_launch(void* const* d_in, const int* in_sizes, int n_in,
                              void* d_out, int out_size)
{
    const float* x    = (const float*)d_in[0];
    const int*   codes[4];
    const float *amax[4], *bias[4], *la[4], *lb[4];
    for (int p = 0; p < 4; p++) {
        codes[p] = (const int*)  d_in[1 + p * 5 + 0];
        amax[p]  = (const float*)d_in[1 + p * 5 + 1];
        bias[p]  = (const float*)d_in[1 + p * 5 + 2];
        la[p]    = (const float*)d_in[1 + p * 5 + 3];
        lb[p]    = (const float*)d_in[1 + p * 5 + 4];
    }
    const float* mask = (const float*)d_in[21];
    float* out = (float*)d_out;

    float *pAa, *pBa, *pQ, *pK, *pV, *pVt, *pAttn, *pXa;
    cudaGetSymbolAddress((void**)&pAa,   g_Aaug);
    cudaGetSymbolAddress((void**)&pBa,   g_Baug);
    cudaGetSymbolAddress((void**)&pQ,    g_q);
    cudaGetSymbolAddress((void**)&pK,    g_k);
    cudaGetSymbolAddress((void**)&pV,    g_v);
    cudaGetSymbolAddress((void**)&pVt,   g_vt);
    cudaGetSymbolAddress((void**)&pAttn, g_attn);
    cudaGetSymbolAddress((void**)&pXa,   g_xa);

    // dynamic smem opt-in (idempotent)
    const int SM256 = 1024 + 2 * (2 * 128 * 128) + 2 * (2 * 256 * 128);  // 197632
    const int SM128 = 1024 + 2 * (2 * 128 * 128) + 2 * (2 * 128 * 128);  // 132096
    cudaFuncSetAttribute(tf32_gemm<256, 0, true>,
        cudaFuncAttributeMaxDynamicSharedMemorySize, SM256);
    cudaFuncSetAttribute(tf32_gemm<256, 0, false>,
        cudaFuncAttributeMaxDynamicSharedMemorySize, SM256);
    cudaFuncSetAttribute(tf32_gemm<256, 1, false>,
        cudaFuncAttributeMaxDynamicSharedMemorySize, SM256);
    cudaFuncSetAttribute(tf32_gemm<128, 2, true>,
        cudaFuncAttributeMaxDynamicSharedMemorySize, SM128);

    const int CKP = KAUG / 64;      // 65 chunks for projections

    // --- A_aug <- rounded x ---
    roundx_kernel<<<NELEM / 4 / 256, 256>>>(x, pAa);

    // --- Q, K, V projections ---
    float* qkv[3] = { pQ, pK, pV };
    for (int p = 0; p < 3; p++) {
        dequant_kernel<<<WELEM / 16 / 256, 256>>>(codes[p], amax[p], pBa);
        tailB_kernel<<<Hd, 64>>>(lb[p], pBa);
        lora_xa_kernel<<<Sq, 256>>>(x, Hd, la[p], pXa);
        tailA_kernel<<<Sq, 64>>>(pXa, pAa);
        tf32_gemm<256, 0, true><<<dim3(16, 8, 1), 256, SM256>>>(
            pAa, KAUG, 0, pBa, KAUG, 0, qkv[p], Hd, 0, bias[p], CKP);
    }

    // --- Attention ---
    tf32_gemm<256, 1, false><<<dim3(4, 8, NHEAD), 256, SM256>>>(
        pQ, Hd, HDIM, pK, Hd, HDIM, pAttn, Sq, (long)Sq * Sq, mask, HDIM / 64);
    softmax_kernel<<<NHEAD * Sq, 256>>>(pAttn);
    vt_kernel<<<dim3(Hd / 32, Sq / 32), dim3(32, 8)>>>(pV, pVt);
    // PV writes the attention output directly into A_aug (stride KAUG)
    tf32_gemm<128, 2, true><<<dim3(1, 8, NHEAD), 256, SM128>>>(
        pAttn, Sq, (long)Sq * Sq, pVt, Sq, (long)HDIM * Sq,
        pAa, KAUG, HDIM, nullptr, Sq / 64);

    // --- Output projection -> d_out ---
    dequant_kernel<<<WELEM / 16 / 256, 256>>>(codes[3], amax[3], pBa);
    tailB_kernel<<<Hd, 64>>>(lb[3], pBa);
    lora_xa_kernel<<<Sq, 256>>>(pAa, KAUG, la[3], pXa);
    tailA_kernel<<<Sq, 64>>>(pXa, pAa);
    tf32_gemm<256, 0, false><<<dim3(16, 8, 1), 256, SM256>>>(
        pAa, KAUG, 0, pBa, KAUG, 0, out, Hd, 0, bias[3], CKP);

    // --- kth values: [x, qh, kh, vh, a, o] ---
    const unsigned long long kN = NELEM / 2;
    const unsigned long long kA = AELEM / 2;
    run_select(x,     NELEM, 12, Hd,   kN, out + NELEM + 0);
    run_select(pQ,    NELEM, 12, Hd,   kN, out + NELEM + 1);
    run_select(pK,    NELEM, 12, Hd,   kN, out + NELEM + 2);
    run_select(pV,    NELEM, 12, Hd,   kN, out + NELEM + 3);
    run_select(pAttn, AELEM, 10, Sq,   kA, out + NELEM + 4);
    run_select(pAa,   NELEM, 12, KAUG, kN, out + NELEM + 5);
}